// round 14
// baseline (speedup 1.0000x reference)
#include <cuda_runtime.h>
#include <cuda_bf16.h>
#include <math_constants.h>
#include <cstdint>

#define NQ 32768
#define NM 2048
#define ND 512
#define BM 128
#define BN 128
#define BK 32
#define KTILES (ND / BK)
#define BKP 40
#define STAGE_ELEMS (128 * BKP)
#define STAGE_BYTES (STAGE_ELEMS * 2)
#define NSTAGE 3
#define SMEM_GEMM (2 * NSTAGE * STAGE_BYTES)   // 61440

#define CAND_CAP 512
#define NCAND 16
#define KTARGET 40
#define CH_FLOATS 128                     // rescore chunk (floats per row)
#define RSTR 132                          // chunk row stride (conflict-free)
#define SMEM_ROWS (NCAND * RSTR * 4)      // 8448 B dynamic

// __device__ globals = sanctioned scratch
__device__ __nv_bfloat16  g_Sb[(size_t)NQ * NM];   // 128 MB bf16 scores
__device__ __nv_bfloat16  g_Ab[(size_t)NQ * ND];
__device__ __nv_bfloat16  g_Bb[(size_t)NM * ND];

__device__ __forceinline__ uint32_t smem_u32(const void* p) {
    uint32_t a;
    asm("{ .reg .u64 t; cvta.to.shared.u64 t, %1; cvt.u32.u64 %0, t; }"
        : "=r"(a) : "l"(p));
    return a;
}
#define CP16(dst, src) \
    asm volatile("cp.async.cg.shared.global [%0], [%1], 16;" \
                 :: "r"(dst), "l"(src) : "memory")
#define CP_COMMIT() asm volatile("cp.async.commit_group;" ::: "memory")
#define CP_WAIT1()  asm volatile("cp.async.wait_group 1;" ::: "memory")

#define LDMX4(r0, r1, r2, r3, addr) \
    asm volatile("ldmatrix.sync.aligned.m8n8.x4.shared.b16 {%0,%1,%2,%3}, [%4];" \
                 : "=r"(r0), "=r"(r1), "=r"(r2), "=r"(r3) : "r"(addr))

#define MMA16816(c, a, b0, b1) \
    asm volatile("mma.sync.aligned.m16n8k16.row.col.f32.bf16.bf16.f32 " \
                 "{%0,%1,%2,%3}, {%4,%5,%6,%7}, {%8,%9}, {%0,%1,%2,%3};" \
                 : "+f"((c)[0]), "+f"((c)[1]), "+f"((c)[2]), "+f"((c)[3]) \
                 : "r"((a)[0]), "r"((a)[1]), "r"((a)[2]), "r"((a)[3]),   \
                   "r"(b0), "r"(b1))

// FMA-pipe exp: 2^(x*log2e), degree-6 poly on frac, rel err ~1e-7, |x|<80.
__device__ __forceinline__ float pexp(float x) {
    float t = x * 1.4426950408889634f;
    float n = rintf(t);
    float f = t - n;
    float p = 1.5403530e-4f;
    p = fmaf(p, f, 1.3333558e-3f);
    p = fmaf(p, f, 9.6181291e-3f);
    p = fmaf(p, f, 5.5504109e-2f);
    p = fmaf(p, f, 2.4022651e-1f);
    p = fmaf(p, f, 6.9314718e-1f);
    p = fmaf(p, f, 1.0f);
    return __int_as_float(((int)n + 127) << 23) * p;
}

// ---------------------------------------------------------------------------
__global__ void tobf16_kernel(const float* __restrict__ X,
                              __nv_bfloat16* __restrict__ Y, int total) {
    int i = blockIdx.x * 256 + threadIdx.x;
    if (i < total) Y[i] = __float2bfloat16(X[i]);
}

// ---------------------------------------------------------------------------
// HMMA GEMM (known-good): scores = Ab @ Bb^T, stored as bf16
// ---------------------------------------------------------------------------
__device__ __forceinline__ void load_stage(uint32_t aBase, uint32_t bBase,
                                           int buf, int kt, int row0, int col0,
                                           int tid) {
#pragma unroll
    for (int i = 0; i < 2; i++) {
        int id = tid + (i << 8);
        int r  = id >> 2;
        int kc = (id & 3) << 3;
        uint32_t da = aBase + buf * STAGE_BYTES + (uint32_t)(r * BKP + kc) * 2;
        const __nv_bfloat16* ga = g_Ab + (size_t)(row0 + r) * ND + kt * BK + kc;
        CP16(da, ga);
        uint32_t db = bBase + buf * STAGE_BYTES + (uint32_t)(r * BKP + kc) * 2;
        const __nv_bfloat16* gb = g_Bb + (size_t)(col0 + r) * ND + kt * BK + kc;
        CP16(db, gb);
    }
}

__global__ __launch_bounds__(256)
void gemm_hmma() {
    extern __shared__ __nv_bfloat16 sm[];
    const int tid = threadIdx.x, lane = tid & 31, wid = tid >> 5;
    const int row0 = blockIdx.y * BM, col0 = blockIdx.x * BN;
    const int mw = (wid >> 1) * 32;
    const int nw = (wid & 1) * 64;
    uint32_t aBase = smem_u32(sm);
    uint32_t bBase = aBase + NSTAGE * STAGE_BYTES;

    const int a_row = lane & 15;
    const int a_k8  = (lane >> 4) << 3;
    const int b_row = (lane & 7) + ((lane >> 4) << 3);
    const int b_k8  = ((lane >> 3) & 1) << 3;

    float c[2][8][4];
#pragma unroll
    for (int mt = 0; mt < 2; mt++)
#pragma unroll
        for (int nt = 0; nt < 8; nt++)
#pragma unroll
            for (int r = 0; r < 4; r++) c[mt][nt][r] = 0.f;

    load_stage(aBase, bBase, 0, 0, row0, col0, tid); CP_COMMIT();
    load_stage(aBase, bBase, 1, 1, row0, col0, tid); CP_COMMIT();

    for (int s = 0; s < KTILES; s++) {
        if (s + 2 < KTILES)
            load_stage(aBase, bBase, (s + 2) % NSTAGE, s + 2, row0, col0, tid);
        CP_COMMIT();
        CP_WAIT1();
        __syncthreads();

        const int buf = s % NSTAGE;
#pragma unroll
        for (int k16 = 0; k16 < BK; k16 += 16) {
            uint32_t a[2][4], b[4][4];
#pragma unroll
            for (int mt = 0; mt < 2; mt++) {
                uint32_t addr = aBase + buf * STAGE_BYTES +
                    (uint32_t)((mw + mt * 16 + a_row) * BKP + k16 + a_k8) * 2;
                LDMX4(a[mt][0], a[mt][1], a[mt][2], a[mt][3], addr);
            }
#pragma unroll
            for (int np = 0; np < 4; np++) {
                uint32_t addr = bBase + buf * STAGE_BYTES +
                    (uint32_t)((nw + np * 16 + b_row) * BKP + k16 + b_k8) * 2;
                LDMX4(b[np][0], b[np][1], b[np][2], b[np][3], addr);
            }
#pragma unroll
            for (int mt = 0; mt < 2; mt++)
#pragma unroll
                for (int nt = 0; nt < 8; nt++)
                    MMA16816(c[mt][nt], a[mt],
                             b[nt >> 1][(nt & 1) * 2],
                             b[nt >> 1][(nt & 1) * 2 + 1]);
        }
        __syncthreads();
    }

#pragma unroll
    for (int mt = 0; mt < 2; mt++) {
        int r0r = row0 + mw + mt * 16 + (lane >> 2);
#pragma unroll
        for (int nt = 0; nt < 8; nt++) {
            int col = col0 + nw + nt * 8 + (lane & 3) * 2;
            __nv_bfloat162 b0 = __floats2bfloat162_rn(c[mt][nt][0], c[mt][nt][1]);
            __nv_bfloat162 b1 = __floats2bfloat162_rn(c[mt][nt][2], c[mt][nt][3]);
            *reinterpret_cast<__nv_bfloat162*>(&g_Sb[(size_t)r0r * NM + col])       = b0;
            *reinterpret_cast<__nv_bfloat162*>(&g_Sb[(size_t)(r0r + 8) * NM + col]) = b1;
        }
    }
}

// ---------------------------------------------------------------------------
// Rowpass v13: NCAND=16 (bf16 top-16 provably/empirically covers exact
// top-10), KTARGET=40; otherwise identical pipeline to v12.
// ---------------------------------------------------------------------------
__global__ __launch_bounds__(256)
void rowpass_kernel(const float* __restrict__ Q, const float* __restrict__ Mi,
                    float* __restrict__ out) {
    extern __shared__ float rowsm[];      // NCAND x RSTR floats (8.4 KB)
    __shared__ float  qs[ND];
    __shared__ float  sv[CAND_CAP];
    __shared__ int    si[CAND_CAP];
    __shared__ int    hist[32];
    __shared__ float  warpmax[8], warpsum[8];
    __shared__ float  cvC[NCAND];
    __shared__ int    ciC[NCAND];
    __shared__ float  ceC[NCAND];
    __shared__ float  selv[10];
    __shared__ int    seli[10];
    __shared__ float  zsh, mxsh, thrsh;
    __shared__ int    cnt, widef;

    const int tid = threadIdx.x, lane = tid & 31, wid = tid >> 5;
    const int row = blockIdx.x;

    // one uint4 = 8 bf16 scores per thread
    uint4 sraw = reinterpret_cast<const uint4*>(g_Sb + (size_t)row * NM)[tid];
    float e0[8];
    {
        const __nv_bfloat162* pp = reinterpret_cast<const __nv_bfloat162*>(&sraw);
#pragma unroll
        for (int h = 0; h < 4; h++) {
            float2 f = __bfloat1622float2(pp[h]);
            e0[2 * h] = f.x; e0[2 * h + 1] = f.y;
        }
    }

    if (tid < 10) { selv[tid] = 0.f; seli[tid] = 0; }
    if (tid < 32) hist[tid] = 0;
    if (tid < NCAND) { cvC[tid] = -CUDART_INF_F; ciC[tid] = 0; }
    if (tid == 0) cnt = 0;
    {
        const float2* q2 = reinterpret_cast<const float2*>(Q + (size_t)row * ND);
        reinterpret_cast<float2*>(qs)[tid] = q2[tid];
    }

    // rowmax + Z (poly-exp) from registers
    float lmax = -CUDART_INF_F, lsum = 0.f;
#pragma unroll
    for (int j = 0; j < 8; j++) {
        lmax = fmaxf(lmax, e0[j]);
        lsum += pexp(e0[j]);
    }
#pragma unroll
    for (int o = 16; o; o >>= 1) {
        lmax = fmaxf(lmax, __shfl_xor_sync(~0u, lmax, o));
        lsum += __shfl_xor_sync(~0u, lsum, o);
    }
    if (lane == 0) { warpmax[wid] = lmax; warpsum[wid] = lsum; }
    __syncthreads();
    if (tid == 0) {
        float m = warpmax[0], z = warpsum[0];
        for (int w = 1; w < 8; w++) { m = fmaxf(m, warpmax[w]); z += warpsum[w]; }
        mxsh = m; zsh = z;
    }
    __syncthreads();
    const float mx = mxsh;

    // histogram (32 bins, width 1/16 over (mx-2, mx]) — warp-aggregated
#pragma unroll
    for (int j = 0; j < 8; j++) {
        float d = (mx - e0[j]) * 16.f;
        bool inr = d < 32.f;
        int bin = inr ? (int)d : 0;
        unsigned act = __ballot_sync(~0u, inr);
        if (inr) {
            unsigned m = __match_any_sync(act, bin);
            int leader = __ffs(m) - 1;
            if (lane == leader) atomicAdd(&hist[bin], __popc(m));
        }
    }
    __syncthreads();
    if (wid == 0) {
        int c = hist[lane];
#pragma unroll
        for (int o = 1; o < 32; o <<= 1) {
            int t = __shfl_up_sync(~0u, c, o);
            if (lane >= o) c += t;
        }
        unsigned m = __ballot_sync(~0u, c >= KTARGET);
        if (lane == 0) {
            if (m) {
                int b = __ffs(m) - 1;
                thrsh = mx - (float)(b + 1) * (1.f / 16.f);
                widef = 0;
            } else widef = 1;
        }
    }
    __syncthreads();

    if (widef) {   // rare: outlier max, widen to (mx-4, mx]
        if (tid < 32) hist[tid] = 0;
        __syncthreads();
#pragma unroll
        for (int j = 0; j < 8; j++) {
            float d = (mx - e0[j]) * 8.f;
            bool inr = d < 32.f;
            int bin = inr ? (int)d : 0;
            unsigned act = __ballot_sync(~0u, inr);
            if (inr) {
                unsigned m = __match_any_sync(act, bin);
                int leader = __ffs(m) - 1;
                if (lane == leader) atomicAdd(&hist[bin], __popc(m));
            }
        }
        __syncthreads();
        if (wid == 0) {
            int c = hist[lane];
#pragma unroll
            for (int o = 1; o < 32; o <<= 1) {
                int t = __shfl_up_sync(~0u, c, o);
                if (lane >= o) c += t;
            }
            unsigned m = __ballot_sync(~0u, c >= KTARGET);
            if (lane == 0) {
                if (m) {
                    int b = __ffs(m) - 1;
                    thrsh = mx - (float)(b + 1) * 0.125f;
                } else thrsh = mx - 4.f;
            }
        }
        __syncthreads();
    }
    const float thr = thrsh;

    // compaction from registers — warp-aggregated offsets
#pragma unroll
    for (int j = 0; j < 8; j++) {
        float x = e0[j];
        int idx = tid * 8 + j;
        bool pred = x > thr;
        unsigned m = __ballot_sync(~0u, pred);
        int nw = __popc(m);
        int base = 0;
        if (lane == 0 && nw) base = atomicAdd(&cnt, nw);
        base = __shfl_sync(~0u, base, 0);
        if (pred) {
            int pos = base + __popc(m & ((1u << lane) - 1u));
            if (pos < CAND_CAP) { sv[pos] = x; si[pos] = idx; }
        }
    }
    __syncthreads();
    const int nsurv = (cnt < CAND_CAP) ? cnt : CAND_CAP;

    // parallel rank-based top-NCAND (value desc, index asc)
    for (int p = tid; p < nsurv; p += 256) {
        float v = sv[p]; int i = si[p];
        int rank = 0;
        for (int q = 0; q < nsurv; q++) {
            float vq = sv[q]; int iq = si[q];
            rank += (vq > v) || (vq == v && iq < i);
        }
        if (rank < NCAND) { cvC[rank] = v; ciC[rank] = i; }
    }

    // chunked staging + EXACT sequential ascending-k fp32 chain.
    float acc = 0.f;
    for (int ch = 0; ch < ND / CH_FLOATS; ch++) {
        __syncthreads();   // rank results visible (ch=0) / prev chains done
        {
            int c0 = wid << 1;                  // warp w -> candidates 2w, 2w+1
#pragma unroll
            for (int r = 0; r < 2; r++) {
                const float4* src = reinterpret_cast<const float4*>(
                    Mi + (size_t)ciC[c0 + r] * ND) + (ch << 5);
                *reinterpret_cast<float4*>(
                    rowsm + (c0 + r) * RSTR + (lane << 2)) = src[lane];
            }
        }
        __syncthreads();
        if (tid < NCAND) {
            const float4* m4 = reinterpret_cast<const float4*>(rowsm + tid * RSTR);
            const float4* q4 = reinterpret_cast<const float4*>(qs) + (ch << 5);
#pragma unroll 8
            for (int it = 0; it < CH_FLOATS / 4; it++) {
                float4 a = q4[it], b = m4[it];
                acc = fmaf(a.x, b.x, acc);
                acc = fmaf(a.y, b.y, acc);
                acc = fmaf(a.z, b.z, acc);
                acc = fmaf(a.w, b.w, acc);
            }
        }
    }
    if (tid < NCAND)
        ceC[tid] = (cvC[tid] > -1e30f) ? acc : -CUDART_INF_F;
    __syncthreads();

    // warp 0: exact ranking of NCAND -> top-10; Z term replacement
    if (wid == 0) {
        float e  = (lane < NCAND) ? ceC[lane] : -CUDART_INF_F;
        int   ii = (lane < NCAND) ? ciC[lane] : 0x7fffffff;
        bool valid = (lane < NCAND) && (e > -1e30f);
        if (valid) {
            int rank = 0;
#pragma unroll
            for (int j = 0; j < NCAND; j++) {
                float ej = ceC[j]; int ij = ciC[j];
                rank += (ej > e) || (ej == e && ij < ii);
            }
            if (rank < 10) { selv[rank] = e; seli[rank] = ii; }
        }
        float dz = valid ? (pexp(e) - pexp(cvC[lane])) : 0.f;
#pragma unroll
        for (int o = 16; o; o >>= 1) dz += __shfl_xor_sync(~0u, dz, o);
        if (lane == 0) zsh += dz;
    }
    __syncthreads();

    const float Z = zsh;
    float p10[10];
#pragma unroll
    for (int j = 0; j < 10; j++) p10[j] = pexp(selv[j]) / Z;
    float wt[5], wb[5], st = 0.f, sb = 0.f;
#pragma unroll
    for (int j = 0; j < 5; j++) { wt[j] = pexp(p10[j]     - p10[0]); st += wt[j]; }
#pragma unroll
    for (int j = 0; j < 5; j++) { wb[j] = pexp(p10[5 + j] - p10[5]); sb += wb[j]; }
    const float rst = 1.f / st, rsb = 1.f / sb;
    int id[10];
#pragma unroll
    for (int j = 0; j < 10; j++) id[j] = seli[j];

    // gather + blend (float2 per thread; 512 = 256*2)
    {
        const int d = tid;
        float2 top = make_float2(0.f, 0.f), bot = make_float2(0.f, 0.f);
#pragma unroll
        for (int j = 0; j < 5; j++) {
            float2 m = reinterpret_cast<const float2*>(Mi + (size_t)id[j] * ND)[d];
            top.x += wt[j] * m.x; top.y += wt[j] * m.y;
        }
#pragma unroll
        for (int j = 0; j < 5; j++) {
            float2 m = reinterpret_cast<const float2*>(Mi + (size_t)id[5 + j] * ND)[d];
            bot.x += wb[j] * m.x; bot.y += wb[j] * m.y;
        }
        float2 q = reinterpret_cast<const float2*>(qs)[d];
        float2 o0, o1;
        o0.x = 0.5f  * q.x + 0.5f  * top.x * rst;
        o0.y = 0.5f  * q.y + 0.5f  * top.y * rst;
        o1.x = 0.01f * q.x + 0.99f * bot.x * rsb;
        o1.y = 0.01f * q.y + 0.99f * bot.y * rsb;
        reinterpret_cast<float2*>(out + (size_t)row * ND)[d] = o0;
        reinterpret_cast<float2*>(out + (size_t)NQ * ND + (size_t)row * ND)[d] = o1;
    }
}

// ---------------------------------------------------------------------------
extern "C" void kernel_launch(void* const* d_in, const int* in_sizes, int n_in,
                              void* d_out, int out_size) {
    const float* Q  = (const float*)d_in[0];
    const float* Mi = (const float*)d_in[1];
    if (n_in >= 2 && in_sizes[0] == NM * ND && in_sizes[1] == NQ * ND) {
        const float* t = Q; Q = Mi; Mi = t;
    }
    float* out = (float*)d_out;

    static int attr_done = 0;
    if (!attr_done) {
        cudaFuncSetAttribute(gemm_hmma,
                             cudaFuncAttributeMaxDynamicSharedMemorySize,
                             SMEM_GEMM);
        cudaFuncSetAttribute(rowpass_kernel,
                             cudaFuncAttributeMaxDynamicSharedMemorySize,
                             SMEM_ROWS);
        attr_done = 1;
    }

    __nv_bfloat16* gA;  cudaGetSymbolAddress((void**)&gA, g_Ab);
    __nv_bfloat16* gB;  cudaGetSymbolAddress((void**)&gB, g_Bb);
    tobf16_kernel<<<(NQ * ND + 255) / 256, 256>>>(Q,  gA, NQ * ND);
    tobf16_kernel<<<(NM * ND + 255) / 256, 256>>>(Mi, gB, NM * ND);

    dim3 gg(NM / BN, NQ / BM);
    gemm_hmma<<<gg, 256, SMEM_GEMM>>>();
    rowpass_kernel<<<NQ, 256, SMEM_ROWS>>>(Q, Mi, out);
}

// round 15
// speedup vs baseline: 1.0868x; 1.0868x over previous
#include <cuda_runtime.h>
#include <cuda_bf16.h>
#include <math_constants.h>
#include <cstdint>

#define NQ 32768
#define NM 2048
#define ND 512
#define BM 128
#define BN 128
#define BK 32
#define KTILES (ND / BK)
#define BKP 40
#define STAGE_ELEMS (128 * BKP)
#define STAGE_BYTES (STAGE_ELEMS * 2)
#define NSTAGE 3
#define SMEM_GEMM (2 * NSTAGE * STAGE_BYTES)   // 61440

#define CAND_CAP 512
#define NCAND 16
#define KTARGET 40
#define CH_FLOATS 128                     // rescore chunk (floats per row)
#define RSTR 132                          // chunk row stride (conflict-free)
#define SMEM_ROWS (NCAND * RSTR * 4)      // 8448 B dynamic

// __device__ globals = sanctioned scratch
__device__ __nv_bfloat16  g_Sb[(size_t)NQ * NM];   // 128 MB bf16 scores
__device__ __nv_bfloat16  g_Ab[(size_t)NQ * ND];
__device__ __nv_bfloat16  g_Bb[(size_t)NM * ND];

__device__ __forceinline__ uint32_t smem_u32(const void* p) {
    uint32_t a;
    asm("{ .reg .u64 t; cvta.to.shared.u64 t, %1; cvt.u32.u64 %0, t; }"
        : "=r"(a) : "l"(p));
    return a;
}
#define CP16(dst, src) \
    asm volatile("cp.async.cg.shared.global [%0], [%1], 16;" \
                 :: "r"(dst), "l"(src) : "memory")
#define CP_COMMIT() asm volatile("cp.async.commit_group;" ::: "memory")
#define CP_WAIT1()  asm volatile("cp.async.wait_group 1;" ::: "memory")

#define LDMX4(r0, r1, r2, r3, addr) \
    asm volatile("ldmatrix.sync.aligned.m8n8.x4.shared.b16 {%0,%1,%2,%3}, [%4];" \
                 : "=r"(r0), "=r"(r1), "=r"(r2), "=r"(r3) : "r"(addr))

#define MMA16816(c, a, b0, b1) \
    asm volatile("mma.sync.aligned.m16n8k16.row.col.f32.bf16.bf16.f32 " \
                 "{%0,%1,%2,%3}, {%4,%5,%6,%7}, {%8,%9}, {%0,%1,%2,%3};" \
                 : "+f"((c)[0]), "+f"((c)[1]), "+f"((c)[2]), "+f"((c)[3]) \
                 : "r"((a)[0]), "r"((a)[1]), "r"((a)[2]), "r"((a)[3]),   \
                   "r"(b0), "r"(b1))

// FMA-pipe exp: 2^(x*log2e), degree-6 poly on frac, rel err ~1e-7, |x|<80.
__device__ __forceinline__ float pexp(float x) {
    float t = x * 1.4426950408889634f;
    float n = rintf(t);
    float f = t - n;
    float p = 1.5403530e-4f;
    p = fmaf(p, f, 1.3333558e-3f);
    p = fmaf(p, f, 9.6181291e-3f);
    p = fmaf(p, f, 5.5504109e-2f);
    p = fmaf(p, f, 2.4022651e-1f);
    p = fmaf(p, f, 6.9314718e-1f);
    p = fmaf(p, f, 1.0f);
    return __int_as_float(((int)n + 127) << 23) * p;
}

// ---------------------------------------------------------------------------
__global__ void tobf16_kernel(const float* __restrict__ X,
                              __nv_bfloat16* __restrict__ Y, int total) {
    int i = blockIdx.x * 256 + threadIdx.x;
    if (i < total) Y[i] = __float2bfloat16(X[i]);
}

// ---------------------------------------------------------------------------
// HMMA GEMM (known-good): scores = Ab @ Bb^T, stored as bf16
// ---------------------------------------------------------------------------
__device__ __forceinline__ void load_stage(uint32_t aBase, uint32_t bBase,
                                           int buf, int kt, int row0, int col0,
                                           int tid) {
#pragma unroll
    for (int i = 0; i < 2; i++) {
        int id = tid + (i << 8);
        int r  = id >> 2;
        int kc = (id & 3) << 3;
        uint32_t da = aBase + buf * STAGE_BYTES + (uint32_t)(r * BKP + kc) * 2;
        const __nv_bfloat16* ga = g_Ab + (size_t)(row0 + r) * ND + kt * BK + kc;
        CP16(da, ga);
        uint32_t db = bBase + buf * STAGE_BYTES + (uint32_t)(r * BKP + kc) * 2;
        const __nv_bfloat16* gb = g_Bb + (size_t)(col0 + r) * ND + kt * BK + kc;
        CP16(db, gb);
    }
}

__global__ __launch_bounds__(256)
void gemm_hmma() {
    extern __shared__ __nv_bfloat16 sm[];
    const int tid = threadIdx.x, lane = tid & 31, wid = tid >> 5;
    const int row0 = blockIdx.y * BM, col0 = blockIdx.x * BN;
    const int mw = (wid >> 1) * 32;
    const int nw = (wid & 1) * 64;
    uint32_t aBase = smem_u32(sm);
    uint32_t bBase = aBase + NSTAGE * STAGE_BYTES;

    const int a_row = lane & 15;
    const int a_k8  = (lane >> 4) << 3;
    const int b_row = (lane & 7) + ((lane >> 4) << 3);
    const int b_k8  = ((lane >> 3) & 1) << 3;

    float c[2][8][4];
#pragma unroll
    for (int mt = 0; mt < 2; mt++)
#pragma unroll
        for (int nt = 0; nt < 8; nt++)
#pragma unroll
            for (int r = 0; r < 4; r++) c[mt][nt][r] = 0.f;

    load_stage(aBase, bBase, 0, 0, row0, col0, tid); CP_COMMIT();
    load_stage(aBase, bBase, 1, 1, row0, col0, tid); CP_COMMIT();

    for (int s = 0; s < KTILES; s++) {
        if (s + 2 < KTILES)
            load_stage(aBase, bBase, (s + 2) % NSTAGE, s + 2, row0, col0, tid);
        CP_COMMIT();
        CP_WAIT1();
        __syncthreads();

        const int buf = s % NSTAGE;
#pragma unroll
        for (int k16 = 0; k16 < BK; k16 += 16) {
            uint32_t a[2][4], b[4][4];
#pragma unroll
            for (int mt = 0; mt < 2; mt++) {
                uint32_t addr = aBase + buf * STAGE_BYTES +
                    (uint32_t)((mw + mt * 16 + a_row) * BKP + k16 + a_k8) * 2;
                LDMX4(a[mt][0], a[mt][1], a[mt][2], a[mt][3], addr);
            }
#pragma unroll
            for (int np = 0; np < 4; np++) {
                uint32_t addr = bBase + buf * STAGE_BYTES +
                    (uint32_t)((nw + np * 16 + b_row) * BKP + k16 + b_k8) * 2;
                LDMX4(b[np][0], b[np][1], b[np][2], b[np][3], addr);
            }
#pragma unroll
            for (int mt = 0; mt < 2; mt++)
#pragma unroll
                for (int nt = 0; nt < 8; nt++)
                    MMA16816(c[mt][nt], a[mt],
                             b[nt >> 1][(nt & 1) * 2],
                             b[nt >> 1][(nt & 1) * 2 + 1]);
        }
        __syncthreads();
    }

#pragma unroll
    for (int mt = 0; mt < 2; mt++) {
        int r0r = row0 + mw + mt * 16 + (lane >> 2);
#pragma unroll
        for (int nt = 0; nt < 8; nt++) {
            int col = col0 + nw + nt * 8 + (lane & 3) * 2;
            __nv_bfloat162 b0 = __floats2bfloat162_rn(c[mt][nt][0], c[mt][nt][1]);
            __nv_bfloat162 b1 = __floats2bfloat162_rn(c[mt][nt][2], c[mt][nt][3]);
            *reinterpret_cast<__nv_bfloat162*>(&g_Sb[(size_t)r0r * NM + col])       = b0;
            *reinterpret_cast<__nv_bfloat162*>(&g_Sb[(size_t)(r0r + 8) * NM + col]) = b1;
        }
    }
}

// ---------------------------------------------------------------------------
// Rowpass v14: identical pipeline to v13 (NCAND=16, KTARGET=40) but with
// __launch_bounds__(256, 8) forcing <=32 regs so 8 CTAs/SM stay resident
// (v13's 34 regs silently dropped residency to 6 CTAs/SM).
// ---------------------------------------------------------------------------
__global__ __launch_bounds__(256, 8)
void rowpass_kernel(const float* __restrict__ Q, const float* __restrict__ Mi,
                    float* __restrict__ out) {
    extern __shared__ float rowsm[];      // NCAND x RSTR floats (8.4 KB)
    __shared__ float  qs[ND];
    __shared__ float  sv[CAND_CAP];
    __shared__ int    si[CAND_CAP];
    __shared__ int    hist[32];
    __shared__ float  warpmax[8], warpsum[8];
    __shared__ float  cvC[NCAND];
    __shared__ int    ciC[NCAND];
    __shared__ float  ceC[NCAND];
    __shared__ float  selv[10];
    __shared__ int    seli[10];
    __shared__ float  zsh, mxsh, thrsh;
    __shared__ int    cnt, widef;

    const int tid = threadIdx.x, lane = tid & 31, wid = tid >> 5;
    const int row = blockIdx.x;

    // one uint4 = 8 bf16 scores per thread
    uint4 sraw = reinterpret_cast<const uint4*>(g_Sb + (size_t)row * NM)[tid];
    float e0[8];
    {
        const __nv_bfloat162* pp = reinterpret_cast<const __nv_bfloat162*>(&sraw);
#pragma unroll
        for (int h = 0; h < 4; h++) {
            float2 f = __bfloat1622float2(pp[h]);
            e0[2 * h] = f.x; e0[2 * h + 1] = f.y;
        }
    }

    if (tid < 10) { selv[tid] = 0.f; seli[tid] = 0; }
    if (tid < 32) hist[tid] = 0;
    if (tid < NCAND) { cvC[tid] = -CUDART_INF_F; ciC[tid] = 0; }
    if (tid == 0) cnt = 0;
    {
        const float2* q2 = reinterpret_cast<const float2*>(Q + (size_t)row * ND);
        reinterpret_cast<float2*>(qs)[tid] = q2[tid];
    }

    // rowmax + Z (poly-exp) from registers
    float lmax = -CUDART_INF_F, lsum = 0.f;
#pragma unroll
    for (int j = 0; j < 8; j++) {
        lmax = fmaxf(lmax, e0[j]);
        lsum += pexp(e0[j]);
    }
#pragma unroll
    for (int o = 16; o; o >>= 1) {
        lmax = fmaxf(lmax, __shfl_xor_sync(~0u, lmax, o));
        lsum += __shfl_xor_sync(~0u, lsum, o);
    }
    if (lane == 0) { warpmax[wid] = lmax; warpsum[wid] = lsum; }
    __syncthreads();
    if (tid == 0) {
        float m = warpmax[0], z = warpsum[0];
        for (int w = 1; w < 8; w++) { m = fmaxf(m, warpmax[w]); z += warpsum[w]; }
        mxsh = m; zsh = z;
    }
    __syncthreads();
    const float mx = mxsh;

    // histogram (32 bins, width 1/16 over (mx-2, mx]) — warp-aggregated
#pragma unroll
    for (int j = 0; j < 8; j++) {
        float d = (mx - e0[j]) * 16.f;
        bool inr = d < 32.f;
        int bin = inr ? (int)d : 0;
        unsigned act = __ballot_sync(~0u, inr);
        if (inr) {
            unsigned m = __match_any_sync(act, bin);
            int leader = __ffs(m) - 1;
            if (lane == leader) atomicAdd(&hist[bin], __popc(m));
        }
    }
    __syncthreads();
    if (wid == 0) {
        int c = hist[lane];
#pragma unroll
        for (int o = 1; o < 32; o <<= 1) {
            int t = __shfl_up_sync(~0u, c, o);
            if (lane >= o) c += t;
        }
        unsigned m = __ballot_sync(~0u, c >= KTARGET);
        if (lane == 0) {
            if (m) {
                int b = __ffs(m) - 1;
                thrsh = mx - (float)(b + 1) * (1.f / 16.f);
                widef = 0;
            } else widef = 1;
        }
    }
    __syncthreads();

    if (widef) {   // rare: outlier max, widen to (mx-4, mx]
        if (tid < 32) hist[tid] = 0;
        __syncthreads();
#pragma unroll
        for (int j = 0; j < 8; j++) {
            float d = (mx - e0[j]) * 8.f;
            bool inr = d < 32.f;
            int bin = inr ? (int)d : 0;
            unsigned act = __ballot_sync(~0u, inr);
            if (inr) {
                unsigned m = __match_any_sync(act, bin);
                int leader = __ffs(m) - 1;
                if (lane == leader) atomicAdd(&hist[bin], __popc(m));
            }
        }
        __syncthreads();
        if (wid == 0) {
            int c = hist[lane];
#pragma unroll
            for (int o = 1; o < 32; o <<= 1) {
                int t = __shfl_up_sync(~0u, c, o);
                if (lane >= o) c += t;
            }
            unsigned m = __ballot_sync(~0u, c >= KTARGET);
            if (lane == 0) {
                if (m) {
                    int b = __ffs(m) - 1;
                    thrsh = mx - (float)(b + 1) * 0.125f;
                } else thrsh = mx - 4.f;
            }
        }
        __syncthreads();
    }
    const float thr = thrsh;

    // compaction from registers — warp-aggregated offsets
#pragma unroll
    for (int j = 0; j < 8; j++) {
        float x = e0[j];
        int idx = tid * 8 + j;
        bool pred = x > thr;
        unsigned m = __ballot_sync(~0u, pred);
        int nw = __popc(m);
        int base = 0;
        if (lane == 0 && nw) base = atomicAdd(&cnt, nw);
        base = __shfl_sync(~0u, base, 0);
        if (pred) {
            int pos = base + __popc(m & ((1u << lane) - 1u));
            if (pos < CAND_CAP) { sv[pos] = x; si[pos] = idx; }
        }
    }
    __syncthreads();
    const int nsurv = (cnt < CAND_CAP) ? cnt : CAND_CAP;

    // parallel rank-based top-NCAND (value desc, index asc)
    for (int p = tid; p < nsurv; p += 256) {
        float v = sv[p]; int i = si[p];
        int rank = 0;
        for (int q = 0; q < nsurv; q++) {
            float vq = sv[q]; int iq = si[q];
            rank += (vq > v) || (vq == v && iq < i);
        }
        if (rank < NCAND) { cvC[rank] = v; ciC[rank] = i; }
    }

    // chunked staging + EXACT sequential ascending-k fp32 chain.
    float acc = 0.f;
    for (int ch = 0; ch < ND / CH_FLOATS; ch++) {
        __syncthreads();   // rank results visible (ch=0) / prev chains done
        {
            int c0 = wid << 1;                  // warp w -> candidates 2w, 2w+1
#pragma unroll
            for (int r = 0; r < 2; r++) {
                const float4* src = reinterpret_cast<const float4*>(
                    Mi + (size_t)ciC[c0 + r] * ND) + (ch << 5);
                *reinterpret_cast<float4*>(
                    rowsm + (c0 + r) * RSTR + (lane << 2)) = src[lane];
            }
        }
        __syncthreads();
        if (tid < NCAND) {
            const float4* m4 = reinterpret_cast<const float4*>(rowsm + tid * RSTR);
            const float4* q4 = reinterpret_cast<const float4*>(qs) + (ch << 5);
#pragma unroll 8
            for (int it = 0; it < CH_FLOATS / 4; it++) {
                float4 a = q4[it], b = m4[it];
                acc = fmaf(a.x, b.x, acc);
                acc = fmaf(a.y, b.y, acc);
                acc = fmaf(a.z, b.z, acc);
                acc = fmaf(a.w, b.w, acc);
            }
        }
    }
    if (tid < NCAND)
        ceC[tid] = (cvC[tid] > -1e30f) ? acc : -CUDART_INF_F;
    __syncthreads();

    // warp 0: exact ranking of NCAND -> top-10; Z term replacement
    if (wid == 0) {
        float e  = (lane < NCAND) ? ceC[lane] : -CUDART_INF_F;
        int   ii = (lane < NCAND) ? ciC[lane] : 0x7fffffff;
        bool valid = (lane < NCAND) && (e > -1e30f);
        if (valid) {
            int rank = 0;
#pragma unroll
            for (int j = 0; j < NCAND; j++) {
                float ej = ceC[j]; int ij = ciC[j];
                rank += (ej > e) || (ej == e && ij < ii);
            }
            if (rank < 10) { selv[rank] = e; seli[rank] = ii; }
        }
        float dz = valid ? (pexp(e) - pexp(cvC[lane])) : 0.f;
#pragma unroll
        for (int o = 16; o; o >>= 1) dz += __shfl_xor_sync(~0u, dz, o);
        if (lane == 0) zsh += dz;
    }
    __syncthreads();

    const float Z = zsh;
    float p10[10];
#pragma unroll
    for (int j = 0; j < 10; j++) p10[j] = pexp(selv[j]) / Z;
    float wt[5], wb[5], st = 0.f, sb = 0.f;
#pragma unroll
    for (int j = 0; j < 5; j++) { wt[j] = pexp(p10[j]     - p10[0]); st += wt[j]; }
#pragma unroll
    for (int j = 0; j < 5; j++) { wb[j] = pexp(p10[5 + j] - p10[5]); sb += wb[j]; }
    const float rst = 1.f / st, rsb = 1.f / sb;
    int id[10];
#pragma unroll
    for (int j = 0; j < 10; j++) id[j] = seli[j];

    // gather + blend (float2 per thread; 512 = 256*2)
    {
        const int d = tid;
        float2 top = make_float2(0.f, 0.f), bot = make_float2(0.f, 0.f);
#pragma unroll
        for (int j = 0; j < 5; j++) {
            float2 m = reinterpret_cast<const float2*>(Mi + (size_t)id[j] * ND)[d];
            top.x += wt[j] * m.x; top.y += wt[j] * m.y;
        }
#pragma unroll
        for (int j = 0; j < 5; j++) {
            float2 m = reinterpret_cast<const float2*>(Mi + (size_t)id[5 + j] * ND)[d];
            bot.x += wb[j] * m.x; bot.y += wb[j] * m.y;
        }
        float2 q = reinterpret_cast<const float2*>(qs)[d];
        float2 o0, o1;
        o0.x = 0.5f  * q.x + 0.5f  * top.x * rst;
        o0.y = 0.5f  * q.y + 0.5f  * top.y * rst;
        o1.x = 0.01f * q.x + 0.99f * bot.x * rsb;
        o1.y = 0.01f * q.y + 0.99f * bot.y * rsb;
        reinterpret_cast<float2*>(out + (size_t)row * ND)[d] = o0;
        reinterpret_cast<float2*>(out + (size_t)NQ * ND + (size_t)row * ND)[d] = o1;
    }
}

// ---------------------------------------------------------------------------
extern "C" void kernel_launch(void* const* d_in, const int* in_sizes, int n_in,
                              void* d_out, int out_size) {
    const float* Q  = (const float*)d_in[0];
    const float* Mi = (const float*)d_in[1];
    if (n_in >= 2 && in_sizes[0] == NM * ND && in_sizes[1] == NQ * ND) {
        const float* t = Q; Q = Mi; Mi = t;
    }
    float* out = (float*)d_out;

    static int attr_done = 0;
    if (!attr_done) {
        cudaFuncSetAttribute(gemm_hmma,
                             cudaFuncAttributeMaxDynamicSharedMemorySize,
                             SMEM_GEMM);
        cudaFuncSetAttribute(rowpass_kernel,
                             cudaFuncAttributeMaxDynamicSharedMemorySize,
                             SMEM_ROWS);
        attr_done = 1;
    }

    __nv_bfloat16* gA;  cudaGetSymbolAddress((void**)&gA, g_Ab);
    __nv_bfloat16* gB;  cudaGetSymbolAddress((void**)&gB, g_Bb);
    tobf16_kernel<<<(NQ * ND + 255) / 256, 256>>>(Q,  gA, NQ * ND);
    tobf16_kernel<<<(NM * ND + 255) / 256, 256>>>(Mi, gB, NM * ND);

    dim3 gg(NM / BN, NQ / BM);
    gemm_hmma<<<gg, 256, SMEM_GEMM>>>();
    rowpass_kernel<<<NQ, 256, SMEM_ROWS>>>(Q, Mi, out);
}

// round 16
// speedup vs baseline: 1.8666x; 1.7175x over previous
#include <cuda_runtime.h>
#include <cuda_bf16.h>
#include <math_constants.h>
#include <cstdint>

#define NQ 32768
#define NM 2048
#define ND 512
#define BM 128
#define BN 128
#define BK 32
#define KTILES (ND / BK)
#define BKP 40
#define STAGE_ELEMS (128 * BKP)
#define STAGE_BYTES (STAGE_ELEMS * 2)
#define NSTAGE 3
#define SMEM_GEMM (2 * NSTAGE * STAGE_BYTES)   // 61440

#define CAND_CAP 512
#define NCAND 16
#define KTARGET 40
#define CH_FLOATS 128                     // rescore chunk (floats per row)
#define RSTR 132                          // chunk row stride (floats)
#define SMEM_ROWS (2 * NCAND * RSTR * 4)  // double-buffered: 16896 B

// __device__ globals = sanctioned scratch
__device__ __nv_bfloat16  g_Sb[(size_t)NQ * NM];   // 128 MB bf16 scores
__device__ __nv_bfloat16  g_Ab[(size_t)NQ * ND];
__device__ __nv_bfloat16  g_Bb[(size_t)NM * ND];

__device__ __forceinline__ uint32_t smem_u32(const void* p) {
    uint32_t a;
    asm("{ .reg .u64 t; cvta.to.shared.u64 t, %1; cvt.u32.u64 %0, t; }"
        : "=r"(a) : "l"(p));
    return a;
}
#define CP16(dst, src) \
    asm volatile("cp.async.cg.shared.global [%0], [%1], 16;" \
                 :: "r"(dst), "l"(src) : "memory")
#define CP_COMMIT() asm volatile("cp.async.commit_group;" ::: "memory")
#define CP_WAIT1()  asm volatile("cp.async.wait_group 1;" ::: "memory")
#define CP_WAIT0()  asm volatile("cp.async.wait_group 0;" ::: "memory")

#define LDMX4(r0, r1, r2, r3, addr) \
    asm volatile("ldmatrix.sync.aligned.m8n8.x4.shared.b16 {%0,%1,%2,%3}, [%4];" \
                 : "=r"(r0), "=r"(r1), "=r"(r2), "=r"(r3) : "r"(addr))

#define MMA16816(c, a, b0, b1) \
    asm volatile("mma.sync.aligned.m16n8k16.row.col.f32.bf16.bf16.f32 " \
                 "{%0,%1,%2,%3}, {%4,%5,%6,%7}, {%8,%9}, {%0,%1,%2,%3};" \
                 : "+f"((c)[0]), "+f"((c)[1]), "+f"((c)[2]), "+f"((c)[3]) \
                 : "r"((a)[0]), "r"((a)[1]), "r"((a)[2]), "r"((a)[3]),   \
                   "r"(b0), "r"(b1))

// accurate FMA-pipe exp (deg-6, rel err ~1e-7): candidates + weights
__device__ __forceinline__ float pexp(float x) {
    float t = x * 1.4426950408889634f;
    float n = rintf(t);
    float f = t - n;
    float p = 1.5403530e-4f;
    p = fmaf(p, f, 1.3333558e-3f);
    p = fmaf(p, f, 9.6181291e-3f);
    p = fmaf(p, f, 5.5504109e-2f);
    p = fmaf(p, f, 2.4022651e-1f);
    p = fmaf(p, f, 6.9314718e-1f);
    p = fmaf(p, f, 1.0f);
    return __int_as_float(((int)n + 127) << 23) * p;
}

// fast FMA-pipe exp (deg-3, rel err ~2e-4): Z streaming only.
// Z tolerance is loose (common factor; weight shift ~ err*0.003).
__device__ __forceinline__ float pexp3(float x) {
    float t = x * 1.4426950408889634f;
    float n = rintf(t);
    float f = t - n;
    float p = 5.700169e-2f;
    p = fmaf(p, f, 2.3918046e-1f);
    p = fmaf(p, f, 6.9340212e-1f);
    p = fmaf(p, f, 9.9999989e-1f);
    return __int_as_float(((int)n + 127) << 23) * p;
}

// ---------------------------------------------------------------------------
__global__ void tobf16_kernel(const float* __restrict__ X,
                              __nv_bfloat16* __restrict__ Y, int total) {
    int i = blockIdx.x * 256 + threadIdx.x;
    if (i < total) Y[i] = __float2bfloat16(X[i]);
}

// ---------------------------------------------------------------------------
// HMMA GEMM (known-good): scores = Ab @ Bb^T, stored as bf16
// ---------------------------------------------------------------------------
__device__ __forceinline__ void load_stage(uint32_t aBase, uint32_t bBase,
                                           int buf, int kt, int row0, int col0,
                                           int tid) {
#pragma unroll
    for (int i = 0; i < 2; i++) {
        int id = tid + (i << 8);
        int r  = id >> 2;
        int kc = (id & 3) << 3;
        uint32_t da = aBase + buf * STAGE_BYTES + (uint32_t)(r * BKP + kc) * 2;
        const __nv_bfloat16* ga = g_Ab + (size_t)(row0 + r) * ND + kt * BK + kc;
        CP16(da, ga);
        uint32_t db = bBase + buf * STAGE_BYTES + (uint32_t)(r * BKP + kc) * 2;
        const __nv_bfloat16* gb = g_Bb + (size_t)(col0 + r) * ND + kt * BK + kc;
        CP16(db, gb);
    }
}

__global__ __launch_bounds__(256)
void gemm_hmma() {
    extern __shared__ __nv_bfloat16 sm[];
    const int tid = threadIdx.x, lane = tid & 31, wid = tid >> 5;
    const int row0 = blockIdx.y * BM, col0 = blockIdx.x * BN;
    const int mw = (wid >> 1) * 32;
    const int nw = (wid & 1) * 64;
    uint32_t aBase = smem_u32(sm);
    uint32_t bBase = aBase + NSTAGE * STAGE_BYTES;

    const int a_row = lane & 15;
    const int a_k8  = (lane >> 4) << 3;
    const int b_row = (lane & 7) + ((lane >> 4) << 3);
    const int b_k8  = ((lane >> 3) & 1) << 3;

    float c[2][8][4];
#pragma unroll
    for (int mt = 0; mt < 2; mt++)
#pragma unroll
        for (int nt = 0; nt < 8; nt++)
#pragma unroll
            for (int r = 0; r < 4; r++) c[mt][nt][r] = 0.f;

    load_stage(aBase, bBase, 0, 0, row0, col0, tid); CP_COMMIT();
    load_stage(aBase, bBase, 1, 1, row0, col0, tid); CP_COMMIT();

    for (int s = 0; s < KTILES; s++) {
        if (s + 2 < KTILES)
            load_stage(aBase, bBase, (s + 2) % NSTAGE, s + 2, row0, col0, tid);
        CP_COMMIT();
        CP_WAIT1();
        __syncthreads();

        const int buf = s % NSTAGE;
#pragma unroll
        for (int k16 = 0; k16 < BK; k16 += 16) {
            uint32_t a[2][4], b[4][4];
#pragma unroll
            for (int mt = 0; mt < 2; mt++) {
                uint32_t addr = aBase + buf * STAGE_BYTES +
                    (uint32_t)((mw + mt * 16 + a_row) * BKP + k16 + a_k8) * 2;
                LDMX4(a[mt][0], a[mt][1], a[mt][2], a[mt][3], addr);
            }
#pragma unroll
            for (int np = 0; np < 4; np++) {
                uint32_t addr = bBase + buf * STAGE_BYTES +
                    (uint32_t)((nw + np * 16 + b_row) * BKP + k16 + b_k8) * 2;
                LDMX4(b[np][0], b[np][1], b[np][2], b[np][3], addr);
            }
#pragma unroll
            for (int mt = 0; mt < 2; mt++)
#pragma unroll
                for (int nt = 0; nt < 8; nt++)
                    MMA16816(c[mt][nt], a[mt],
                             b[nt >> 1][(nt & 1) * 2],
                             b[nt >> 1][(nt & 1) * 2 + 1]);
        }
        __syncthreads();
    }

#pragma unroll
    for (int mt = 0; mt < 2; mt++) {
        int r0r = row0 + mw + mt * 16 + (lane >> 2);
#pragma unroll
        for (int nt = 0; nt < 8; nt++) {
            int col = col0 + nw + nt * 8 + (lane & 3) * 2;
            __nv_bfloat162 b0 = __floats2bfloat162_rn(c[mt][nt][0], c[mt][nt][1]);
            __nv_bfloat162 b1 = __floats2bfloat162_rn(c[mt][nt][2], c[mt][nt][3]);
            *reinterpret_cast<__nv_bfloat162*>(&g_Sb[(size_t)r0r * NM + col])       = b0;
            *reinterpret_cast<__nv_bfloat162*>(&g_Sb[(size_t)(r0r + 8) * NM + col]) = b1;
        }
    }
}

// ---------------------------------------------------------------------------
// Rowpass v15: deg-3 exp for Z stream; narrow histogram (mx-1, 1/32 bins);
// cp.async double-buffered candidate staging overlapping the sequential
// ascending-k fp32 rescore chains (chain order bit-identical to v13/v14).
// ---------------------------------------------------------------------------
__global__ __launch_bounds__(256, 8)
void rowpass_kernel(const float* __restrict__ Q, const float* __restrict__ Mi,
                    float* __restrict__ out) {
    extern __shared__ float rowsm[];      // 2 x NCAND x RSTR floats
    __shared__ float  qs[ND];
    __shared__ float  sv[CAND_CAP];
    __shared__ int    si[CAND_CAP];
    __shared__ int    hist[32];
    __shared__ float  warpmax[8], warpsum[8];
    __shared__ float  cvC[NCAND];
    __shared__ int    ciC[NCAND];
    __shared__ float  ceC[NCAND];
    __shared__ float  selv[10];
    __shared__ int    seli[10];
    __shared__ float  zsh, mxsh, thrsh;
    __shared__ int    cnt, widef;

    const int tid = threadIdx.x, lane = tid & 31, wid = tid >> 5;
    const int row = blockIdx.x;

    // one uint4 = 8 bf16 scores per thread
    uint4 sraw = reinterpret_cast<const uint4*>(g_Sb + (size_t)row * NM)[tid];
    float e0[8];
    {
        const __nv_bfloat162* pp = reinterpret_cast<const __nv_bfloat162*>(&sraw);
#pragma unroll
        for (int h = 0; h < 4; h++) {
            float2 f = __bfloat1622float2(pp[h]);
            e0[2 * h] = f.x; e0[2 * h + 1] = f.y;
        }
    }

    if (tid < 10) { selv[tid] = 0.f; seli[tid] = 0; }
    if (tid < 32) hist[tid] = 0;
    if (tid < NCAND) { cvC[tid] = -CUDART_INF_F; ciC[tid] = 0; }
    if (tid == 0) cnt = 0;
    {
        const float2* q2 = reinterpret_cast<const float2*>(Q + (size_t)row * ND);
        reinterpret_cast<float2*>(qs)[tid] = q2[tid];
    }

    // rowmax + Z (deg-3 poly exp) from registers
    float lmax = -CUDART_INF_F, lsum = 0.f;
#pragma unroll
    for (int j = 0; j < 8; j++) {
        lmax = fmaxf(lmax, e0[j]);
        lsum += pexp3(e0[j]);
    }
#pragma unroll
    for (int o = 16; o; o >>= 1) {
        lmax = fmaxf(lmax, __shfl_xor_sync(~0u, lmax, o));
        lsum += __shfl_xor_sync(~0u, lsum, o);
    }
    if (lane == 0) { warpmax[wid] = lmax; warpsum[wid] = lsum; }
    __syncthreads();
    if (tid == 0) {
        float m = warpmax[0], z = warpsum[0];
        for (int w = 1; w < 8; w++) { m = fmaxf(m, warpmax[w]); z += warpsum[w]; }
        mxsh = m; zsh = z;
    }
    __syncthreads();
    const float mx = mxsh;

    // histogram: 32 bins of width 1/32 over (mx-1, mx] — warp-aggregated
#pragma unroll
    for (int j = 0; j < 8; j++) {
        float d = (mx - e0[j]) * 32.f;
        bool inr = d < 32.f;
        int bin = inr ? (int)d : 0;
        unsigned act = __ballot_sync(~0u, inr);
        if (inr) {
            unsigned m = __match_any_sync(act, bin);
            int leader = __ffs(m) - 1;
            if (lane == leader) atomicAdd(&hist[bin], __popc(m));
        }
    }
    __syncthreads();
    if (wid == 0) {
        int c = hist[lane];
#pragma unroll
        for (int o = 1; o < 32; o <<= 1) {
            int t = __shfl_up_sync(~0u, c, o);
            if (lane >= o) c += t;
        }
        unsigned m = __ballot_sync(~0u, c >= KTARGET);
        if (lane == 0) {
            if (m) {
                int b = __ffs(m) - 1;
                thrsh = mx - (float)(b + 1) * (1.f / 32.f);
                widef = 0;
            } else widef = 1;
        }
    }
    __syncthreads();

    if (widef) {   // outlier max: widen to (mx-4, mx]
        if (tid < 32) hist[tid] = 0;
        __syncthreads();
#pragma unroll
        for (int j = 0; j < 8; j++) {
            float d = (mx - e0[j]) * 8.f;
            bool inr = d < 32.f;
            int bin = inr ? (int)d : 0;
            unsigned act = __ballot_sync(~0u, inr);
            if (inr) {
                unsigned m = __match_any_sync(act, bin);
                int leader = __ffs(m) - 1;
                if (lane == leader) atomicAdd(&hist[bin], __popc(m));
            }
        }
        __syncthreads();
        if (wid == 0) {
            int c = hist[lane];
#pragma unroll
            for (int o = 1; o < 32; o <<= 1) {
                int t = __shfl_up_sync(~0u, c, o);
                if (lane >= o) c += t;
            }
            unsigned m = __ballot_sync(~0u, c >= KTARGET);
            if (lane == 0) {
                if (m) {
                    int b = __ffs(m) - 1;
                    thrsh = mx - (float)(b + 1) * 0.125f;
                } else thrsh = mx - 4.f;
            }
        }
        __syncthreads();
    }
    const float thr = thrsh;

    // compaction from registers — warp-aggregated offsets
#pragma unroll
    for (int j = 0; j < 8; j++) {
        float x = e0[j];
        int idx = tid * 8 + j;
        bool pred = x > thr;
        unsigned m = __ballot_sync(~0u, pred);
        int nw = __popc(m);
        int base = 0;
        if (lane == 0 && nw) base = atomicAdd(&cnt, nw);
        base = __shfl_sync(~0u, base, 0);
        if (pred) {
            int pos = base + __popc(m & ((1u << lane) - 1u));
            if (pos < CAND_CAP) { sv[pos] = x; si[pos] = idx; }
        }
    }
    __syncthreads();
    const int nsurv = (cnt < CAND_CAP) ? cnt : CAND_CAP;

    // parallel rank-based top-NCAND (value desc, index asc)
    for (int p = tid; p < nsurv; p += 256) {
        float v = sv[p]; int i = si[p];
        int rank = 0;
        for (int q = 0; q < nsurv; q++) {
            float vq = sv[q]; int iq = si[q];
            rank += (vq > v) || (vq == v && iq < i);
        }
        if (rank < NCAND) { cvC[rank] = v; ciC[rank] = i; }
    }
    __syncthreads();   // ciC ready for staging

    // cp.async double-buffered staging + EXACT sequential ascending-k chain.
    const uint32_t rbase = smem_u32(rowsm);
    const int c0 = wid << 1;           // warp w stages candidates 2w, 2w+1
    {
#pragma unroll
        for (int r = 0; r < 2; r++) {
            const char* src = reinterpret_cast<const char*>(
                Mi + (size_t)ciC[c0 + r] * ND) + (lane << 4);
            CP16(rbase + (uint32_t)(c0 + r) * (RSTR * 4) + (lane << 4), src);
        }
        CP_COMMIT();
    }
    float acc = 0.f;
#pragma unroll
    for (int ch = 0; ch < ND / CH_FLOATS; ch++) {
        if (ch < ND / CH_FLOATS - 1) {
#pragma unroll
            for (int r = 0; r < 2; r++) {
                const char* src = reinterpret_cast<const char*>(
                    Mi + (size_t)ciC[c0 + r] * ND + (ch + 1) * CH_FLOATS)
                    + (lane << 4);
                CP16(rbase + (uint32_t)(((ch + 1) & 1) * NCAND + c0 + r) *
                         (RSTR * 4) + (lane << 4), src);
            }
            CP_COMMIT();
            CP_WAIT1();
        } else {
            CP_WAIT0();
        }
        __syncthreads();
        if (tid < NCAND) {
            const float4* m4 = reinterpret_cast<const float4*>(
                rowsm + ((ch & 1) * NCAND + tid) * RSTR);
            const float4* q4 = reinterpret_cast<const float4*>(qs) + (ch << 5);
#pragma unroll 8
            for (int it = 0; it < CH_FLOATS / 4; it++) {
                float4 a = q4[it], b = m4[it];
                acc = fmaf(a.x, b.x, acc);
                acc = fmaf(a.y, b.y, acc);
                acc = fmaf(a.z, b.z, acc);
                acc = fmaf(a.w, b.w, acc);
            }
        }
        __syncthreads();
    }
    if (tid < NCAND)
        ceC[tid] = (cvC[tid] > -1e30f) ? acc : -CUDART_INF_F;
    __syncthreads();

    // warp 0: exact ranking of NCAND -> top-10; Z term replacement
    if (wid == 0) {
        float e  = (lane < NCAND) ? ceC[lane] : -CUDART_INF_F;
        int   ii = (lane < NCAND) ? ciC[lane] : 0x7fffffff;
        bool valid = (lane < NCAND) && (e > -1e30f);
        if (valid) {
            int rank = 0;
#pragma unroll
            for (int j = 0; j < NCAND; j++) {
                float ej = ceC[j]; int ij = ciC[j];
                rank += (ej > e) || (ej == e && ij < ii);
            }
            if (rank < 10) { selv[rank] = e; seli[rank] = ii; }
        }
        // replace approx terms (pexp3 of bf16 score) with exact (pexp of fp32)
        float dz = valid ? (pexp(e) - pexp3(cvC[lane])) : 0.f;
#pragma unroll
        for (int o = 16; o; o >>= 1) dz += __shfl_xor_sync(~0u, dz, o);
        if (lane == 0) zsh += dz;
    }
    __syncthreads();

    const float Z = zsh;
    float p10[10];
#pragma unroll
    for (int j = 0; j < 10; j++) p10[j] = pexp(selv[j]) / Z;
    float wt[5], wb[5], st = 0.f, sb = 0.f;
#pragma unroll
    for (int j = 0; j < 5; j++) { wt[j] = pexp(p10[j]     - p10[0]); st += wt[j]; }
#pragma unroll
    for (int j = 0; j < 5; j++) { wb[j] = pexp(p10[5 + j] - p10[5]); sb += wb[j]; }
    const float rst = 1.f / st, rsb = 1.f / sb;
    int id[10];
#pragma unroll
    for (int j = 0; j < 10; j++) id[j] = seli[j];

    // gather + blend (float2 per thread; 512 = 256*2)
    {
        const int d = tid;
        float2 top = make_float2(0.f, 0.f), bot = make_float2(0.f, 0.f);
#pragma unroll
        for (int j = 0; j < 5; j++) {
            float2 m = reinterpret_cast<const float2*>(Mi + (size_t)id[j] * ND)[d];
            top.x += wt[j] * m.x; top.y += wt[j] * m.y;
        }
#pragma unroll
        for (int j = 0; j < 5; j++) {
            float2 m = reinterpret_cast<const float2*>(Mi + (size_t)id[5 + j] * ND)[d];
            bot.x += wb[j] * m.x; bot.y += wb[j] * m.y;
        }
        float2 q = reinterpret_cast<const float2*>(qs)[d];
        float2 o0, o1;
        o0.x = 0.5f  * q.x + 0.5f  * top.x * rst;
        o0.y = 0.5f  * q.y + 0.5f  * top.y * rst;
        o1.x = 0.01f * q.x + 0.99f * bot.x * rsb;
        o1.y = 0.01f * q.y + 0.99f * bot.y * rsb;
        reinterpret_cast<float2*>(out + (size_t)row * ND)[d] = o0;
        reinterpret_cast<float2*>(out + (size_t)NQ * ND + (size_t)row * ND)[d] = o1;
    }
}

// ---------------------------------------------------------------------------
extern "C" void kernel_launch(void* const* d_in, const int* in_sizes, int n_in,
                              void* d_out, int out_size) {
    const float* Q  = (const float*)d_in[0];
    const float* Mi = (const float*)d_in[1];
    if (n_in >= 2 && in_sizes[0] == NM * ND && in_sizes[1] == NQ * ND) {
        const float* t = Q; Q = Mi; Mi = t;
    }
    float* out = (float*)d_out;

    static int attr_done = 0;
    if (!attr_done) {
        cudaFuncSetAttribute(gemm_hmma,
                             cudaFuncAttributeMaxDynamicSharedMemorySize,
                             SMEM_GEMM);
        cudaFuncSetAttribute(rowpass_kernel,
                             cudaFuncAttributeMaxDynamicSharedMemorySize,
                             SMEM_ROWS);
        attr_done = 1;
    }

    __nv_bfloat16* gA;  cudaGetSymbolAddress((void**)&gA, g_Ab);
    __nv_bfloat16* gB;  cudaGetSymbolAddress((void**)&gB, g_Bb);
    tobf16_kernel<<<(NQ * ND + 255) / 256, 256>>>(Q,  gA, NQ * ND);
    tobf16_kernel<<<(NM * ND + 255) / 256, 256>>>(Mi, gB, NM * ND);

    dim3 gg(NM / BN, NQ / BM);
    gemm_hmma<<<gg, 256, SMEM_GEMM>>>();
    rowpass_kernel<<<NQ, 256, SMEM_ROWS>>>(Q, Mi, out);
}